// round 16
// baseline (speedup 1.0000x reference)
#include <cuda_runtime.h>
#include <cuda_fp16.h>
#include <math.h>
#include <stdint.h>

#define BB 8
#define NN 1024
#define CC 1024
#define HH 16
#define DD 64

// Scratch (allocation-free rule: __device__ globals)
__device__ __half g_q[BB * HH * NN * DD];
__device__ __half g_k[BB * HH * NN * DD];
__device__ __half g_v[BB * HH * NN * DD];
__device__ __half g_attn[BB * NN * CC];
__device__ __half g_x[BB * NN * CC];
__device__ __half g_wqkv[CC * 3 * CC];    // [k][n] f16 (natural layout)
__device__ __half g_wproj[CC * CC];       // [k][n] f16

__device__ __forceinline__ void mma16(float* d, const uint32_t* a, uint32_t b0,
                                      uint32_t b1) {
    asm volatile(
        "mma.sync.aligned.m16n8k16.row.col.f32.f16.f16.f32 "
        "{%0,%1,%2,%3}, {%4,%5,%6,%7}, {%8,%9}, {%0,%1,%2,%3};\n"
        : "+f"(d[0]), "+f"(d[1]), "+f"(d[2]), "+f"(d[3])
        : "r"(a[0]), "r"(a[1]), "r"(a[2]), "r"(a[3]), "r"(b0), "r"(b1));
}

__device__ __forceinline__ void ldm4a(uint32_t* r, uint32_t a) {
    asm volatile(
        "ldmatrix.sync.aligned.m8n8.x4.shared.b16 {%0,%1,%2,%3}, [%4];\n"
        : "=r"(r[0]), "=r"(r[1]), "=r"(r[2]), "=r"(r[3])
        : "r"(a));
}
__device__ __forceinline__ void ldm4(uint32_t* r, const __half* p) {
    ldm4a(r, (uint32_t)__cvta_generic_to_shared(p));
}
__device__ __forceinline__ void ldm4ta(uint32_t* r, uint32_t a) {
    asm volatile(
        "ldmatrix.sync.aligned.m8n8.x4.trans.shared.b16 {%0,%1,%2,%3}, [%4];\n"
        : "=r"(r[0]), "=r"(r[1]), "=r"(r[2]), "=r"(r[3])
        : "r"(a));
}
__device__ __forceinline__ void ldm4t(uint32_t* r, const __half* p) {
    ldm4ta(r, (uint32_t)__cvta_generic_to_shared(p));
}

// exp2 of two pre-scaled floats, packed f16x2 {lo=exp2(a), hi=exp2(b)}
__device__ __forceinline__ uint32_t exp2h2(float a, float b) {
    uint32_t d;
    asm("{\n\t.reg .b32 t;\n\t"
        "cvt.rn.f16x2.f32 t, %2, %1;\n\t"
        "ex2.approx.f16x2 %0, t;\n\t}"
        : "=r"(d)
        : "f"(a), "f"(b));
    return d;
}

__device__ __forceinline__ void cp16(__half* smem, const __half* gmem) {
    uint32_t s = (uint32_t)__cvta_generic_to_shared(smem);
    asm volatile("cp.async.cg.shared.global [%0], [%1], 16;\n" ::"r"(s), "l"(gmem)
                 : "memory");
}
__device__ __forceinline__ void cp_commit() {
    asm volatile("cp.async.commit_group;\n" ::: "memory");
}
template <int N>
__device__ __forceinline__ void cp_wait() {
    asm volatile("cp.async.wait_group %0;\n" ::"n"(N) : "memory");
}

// ---------------------------------------------------------------------------
// Merged pre-pass: f32 -> f16 for x, w_qkv, w_proj in one launch.
// ---------------------------------------------------------------------------
__global__ void conv_all(const float* __restrict__ x, const float* __restrict__ wq,
                         const float* __restrict__ wp, __half* __restrict__ gx,
                         __half* __restrict__ gwq, __half* __restrict__ gwp) {
    int bb = blockIdx.x;
    const float* in;
    __half* out;
    int base;
    if (bb < 8192) {
        in = x; out = gx; base = bb;
    } else if (bb < 11264) {
        in = wq; out = gwq; base = bb - 8192;
    } else {
        in = wp; out = gwp; base = bb - 11264;
    }
    int i = base * 256 + threadIdx.x;
    float4 v = ((const float4*)in)[i];
    ((__half2*)out)[2 * i] = __floats2half2_rn(v.x, v.y);
    ((__half2*)out)[2 * i + 1] = __floats2half2_rn(v.z, v.w);
}

// ---------------------------------------------------------------------------
// fp16 mma.sync GEMM. CTA tile 128 x TN (96 qkv / 128 proj), 8 warps (4m x 2n),
// 6-stage k32 cp.async ring, TWO stages consumed per barrier (k64 per iter,
// 16 iterations): halves the barrier-convoy count at unchanged prefetch depth.
// A [m][k] ldmatrix, B [k][n] natural layout via ldmatrix.trans.
// MODE 0: Y = x @ w_qkv, fused RoPE -> g_q/g_k/g_v (f16).
// MODE 1: out = attn @ w_proj + bias (f32).
// ---------------------------------------------------------------------------
#define TSH 40
#define A_STG_H (128 * TSH)
#define A_STG_B (A_STG_H * 2)
#define NSTG 6

template <int MODE, int TN>
__global__ __launch_bounds__(256, 2) void gemm_f16(const float* __restrict__ bias,
                                                   float* __restrict__ out) {
    constexpr int BSTR = TN + 8;
    constexpr int B_STG_H = 32 * BSTR;
    constexpr int B_STG_B = B_STG_H * 2;
    constexpr int NB = TN / 32;
    constexpr int NACC = TN / 16;
    constexpr int NCOL = (MODE == 0) ? 3072 : 1024;
    extern __shared__ __half smh[];

    const int tid = threadIdx.x;
    const int bx = blockIdx.x, by = blockIdx.y;
    const int lane = tid & 31, warp = tid >> 5;
    const int wm = warp & 3, wn = warp >> 2;
    const int r = lane >> 2, q = lane & 3;
    const int lrow = lane & 15, lcol = (lane >> 4) * 8;

    const uint32_t sA = (uint32_t)__cvta_generic_to_shared(smh);
    const uint32_t aBase = sA + ((wm * 32 + lrow) * TSH + lcol) * 2;
    const uint32_t bBase =
        sA + NSTG * A_STG_B + (lrow * BSTR + wn * (TN / 2) + lcol) * 2;

    float acc[2][NACC][4];
#pragma unroll
    for (int mi = 0; mi < 2; mi++)
#pragma unroll
        for (int ni = 0; ni < NACC; ni++)
#pragma unroll
            for (int c = 0; c < 4; c++) acc[mi][ni][c] = 0.f;

    const int srow = tid >> 1, soff = (tid & 1) * 16;
    const __half* Ap = (MODE == 0) ? g_x : g_attn;
    const __half* Bp = (MODE == 0) ? g_wqkv : g_wproj;
    const __half* Ag = Ap + (size_t)(by * 128 + srow) * 1024 + soff;
    __half* AsW = smh + srow * TSH + soff;

    constexpr int BCH = TN / 8;  // 16B chunks per B k-row
    const int b0r = tid / BCH, b0c = (tid % BCH) * 8;
    const int b1r = (tid + 256) / BCH, b1c = ((tid + 256) % BCH) * 8;
    const bool b1act = (TN == 128) || ((TN == 96) && (tid < 128));
    const __half* Bg = Bp + (size_t)bx * TN;
    __half* BsW = smh + NSTG * A_STG_H;

    auto load_stage = [&](int st, int ks32) {
        const int k0 = ks32 * 32;
#pragma unroll
        for (int l = 0; l < 2; l++)
            cp16(AsW + st * A_STG_H + l * 8, Ag + k0 + l * 8);
        cp16(BsW + st * B_STG_H + b0r * BSTR + b0c,
             Bg + (size_t)(k0 + b0r) * NCOL + b0c);
        if (b1act)
            cp16(BsW + st * B_STG_H + b1r * BSTR + b1c,
                 Bg + (size_t)(k0 + b1r) * NCOL + b1c);
        cp_commit();
    };

    load_stage(0, 0);
    load_stage(1, 1);
    load_stage(2, 2);
    load_stage(3, 3);

    // 16 iterations; each consumes k32 stages 2it and 2it+1.
    for (int it = 0; it < 16; it++) {
        if (it < 15) cp_wait<2>(); else cp_wait<0>();
        __syncthreads();
        if (it + 2 < 16) {
            load_stage((2 * it + 4) % NSTG, 2 * it + 4);
            load_stage((2 * it + 5) % NSTG, 2 * it + 5);
        }

#pragma unroll
        for (int sub = 0; sub < 2; sub++) {
            const int st = (2 * it + sub) % NSTG;
            const uint32_t aCur = aBase + st * A_STG_B;
            const uint32_t bCur = bBase + st * B_STG_B;

            uint32_t fa0[2][4], fa1[2][4], fb0[NB][4], fb1[NB][4];
#pragma unroll
            for (int mi = 0; mi < 2; mi++)
                ldm4a(fa0[mi], aCur + mi * (16 * TSH * 2));
#pragma unroll
            for (int nb = 0; nb < NB; nb++) ldm4ta(fb0[nb], bCur + nb * 32);
#pragma unroll
            for (int mi = 0; mi < 2; mi++)
                ldm4a(fa1[mi], aCur + mi * (16 * TSH * 2) + 32);
#pragma unroll
            for (int nb = 0; nb < NB; nb++)
                ldm4ta(fb1[nb], bCur + 16 * BSTR * 2 + nb * 32);

#pragma unroll
            for (int mi = 0; mi < 2; mi++)
#pragma unroll
                for (int nb = 0; nb < NB; nb++) {
                    mma16(acc[mi][2 * nb], fa0[mi], fb0[nb][0], fb0[nb][1]);
                    mma16(acc[mi][2 * nb + 1], fa0[mi], fb0[nb][2], fb0[nb][3]);
                }
#pragma unroll
            for (int mi = 0; mi < 2; mi++)
#pragma unroll
                for (int nb = 0; nb < NB; nb++) {
                    mma16(acc[mi][2 * nb], fa1[mi], fb1[nb][0], fb1[nb][1]);
                    mma16(acc[mi][2 * nb + 1], fa1[mi], fb1[nb][2], fb1[nb][3]);
                }
        }
    }

#pragma unroll
    for (int mi = 0; mi < 2; mi++)
#pragma unroll
        for (int ni = 0; ni < NACC; ni++)
#pragma unroll
            for (int ch = 0; ch < 2; ch++) {
                int gr = by * 128 + wm * 32 + mi * 16 + ch * 8 + r;
                int gc = bx * TN + wn * (TN / 2) + ni * 8 + 2 * q;
                float v1 = acc[mi][ni][ch * 2], v2 = acc[mi][ni][ch * 2 + 1];
                if (MODE == 1) {
                    float2 o = make_float2(v1 + bias[gc], v2 + bias[gc + 1]);
                    *(float2*)&out[(size_t)gr * 1024 + gc] = o;
                } else {
                    int b = gr >> 10, n = gr & 1023;
                    int which = gc >> 10, within = gc & 1023;
                    int h = within >> 6, d = within & 63;
                    size_t idx = (((size_t)(b * HH + h)) * NN + n) * DD + d;
                    if (which == 2) {
                        __half2 o = __floats2half2_rn(v1, v2);
                        *(__half2*)&g_v[idx] = o;
                    } else {
                        int p = d >> 1;
                        float omega = exp2f(-0.41524101186f * (float)p);
                        float ang = (float)n * omega;
                        float si, co;
                        __sincosf(ang, &si, &co);
                        __half2 o = __floats2half2_rn(v1 * co - v2 * si,
                                                      v2 * co + v1 * si);
                        __half* dst = which ? g_k : g_q;
                        *(__half2*)&dst[idx] = o;
                    }
                }
            }
}

// ---------------------------------------------------------------------------
// fp16 mma.sync flash attention (frozen from R13). CTA = 128 q-rows.
// ---------------------------------------------------------------------------
#define KV2_H (128 * 72)
#define ATTN_SMEM (6 * KV2_H * 2)

__global__ __launch_bounds__(256, 2) void attn_f16() {
    extern __shared__ __half smh[];
    __half* Ks = smh;                 // [3][128][72]
    __half* Vs = smh + 3 * KV2_H;     // [3][128][72]

    const int tid = threadIdx.x;
    const int lane = tid & 31, w = tid >> 5;
    const int r = lane >> 2, q = lane & 3;
    const int lrow = lane & 15, lcol = (lane >> 4) * 8;
    const int qt = blockIdx.x, h = blockIdx.y, b = blockIdx.z;

    const __half* Qg = g_q + ((size_t)(b * HH + h) * NN + qt * 128) * DD;
    const __half* Kg = g_k + (size_t)(b * HH + h) * NN * DD;
    const __half* Vg = g_v + (size_t)(b * HH + h) * NN * DD;

    auto load_kv2 = [&](int kt2, int st) {
#pragma unroll
        for (int l = 0; l < 4; l++) {
            int c = tid + 256 * l;
            int row = c >> 3, ch = c & 7;
            cp16(&Ks[st * KV2_H + row * 72 + ch * 8],
                 Kg + (size_t)(kt2 * 128 + row) * DD + ch * 8);
            cp16(&Vs[st * KV2_H + row * 72 + ch * 8],
                 Vg + (size_t)(kt2 * 128 + row) * DD + ch * 8);
        }
        cp_commit();
    };

    load_kv2(0, 0);
    load_kv2(1, 1);

    uint32_t qf[4][4];
#pragma unroll
    for (int j = 0; j < 4; j++) {
        qf[j][0] = *(const uint32_t*)&Qg[(w * 16 + r) * DD + j * 16 + 2 * q];
        qf[j][1] = *(const uint32_t*)&Qg[(w * 16 + 8 + r) * DD + j * 16 + 2 * q];
        qf[j][2] = *(const uint32_t*)&Qg[(w * 16 + r) * DD + j * 16 + 8 + 2 * q];
        qf[j][3] = *(const uint32_t*)&Qg[(w * 16 + 8 + r) * DD + j * 16 + 8 + 2 * q];
    }

    float Oa[8][4];
#pragma unroll
    for (int ni = 0; ni < 8; ni++)
#pragma unroll
        for (int c = 0; c < 4; c++) Oa[ni][c] = 0.f;
    float lsum0 = 0.f, lsum1 = 0.f;
    const float SC = 0.18033688011f;  // 0.125 * log2(e)

    for (int i = 0; i < 8; i++) {
        if (i < 6) cp_wait<1>(); else cp_wait<0>();
        __syncthreads();
        if (i + 2 < 8) load_kv2(i + 2, (i + 2) % 3);

        const __half* Kc = Ks + (i % 3) * KV2_H;
        const __half* Vc = Vs + (i % 3) * KV2_H;

        float rs0 = 0.f, rs1 = 0.f;
#pragma unroll
        for (int half = 0; half < 2; half++) {
            const int ro = half * 64;
            float s[8][4];
#pragma unroll
            for (int ni = 0; ni < 8; ni++)
#pragma unroll
                for (int c = 0; c < 4; c++) s[ni][c] = 0.f;
#pragma unroll
            for (int j = 0; j < 4; j++) {
                uint32_t kf[4][4];
#pragma unroll
                for (int nb = 0; nb < 4; nb++)
                    ldm4(kf[nb],
                         &Kc[(ro + nb * 16 + lrow) * 72 + j * 16 + lcol]);
#pragma unroll
                for (int nb = 0; nb < 4; nb++) {
                    mma16(s[2 * nb], qf[j], kf[nb][0], kf[nb][2]);
                    mma16(s[2 * nb + 1], qf[j], kf[nb][1], kf[nb][3]);
                }
            }

#pragma unroll
            for (int j = 0; j < 4; j++) {
                uint32_t pa[4];
                pa[0] = exp2h2(s[2 * j][0] * SC, s[2 * j][1] * SC);
                pa[1] = exp2h2(s[2 * j][2] * SC, s[2 * j][3] * SC);
                pa[2] = exp2h2(s[2 * j + 1][0] * SC, s[2 * j + 1][1] * SC);
                pa[3] = exp2h2(s[2 * j + 1][2] * SC, s[2 * j + 1][3] * SC);
                __half2 h0 = __hadd2(*(__half2*)&pa[0], *(__half2*)&pa[2]);
                __half2 h1 = __hadd2(*(__half2*)&pa[1], *(__half2*)&pa[3]);
                rs0 += __low2float(h0) + __high2float(h0);
                rs1 += __low2float(h1) + __high2float(h1);

                uint32_t vf[4][4];
#pragma unroll
                for (int g = 0; g < 4; g++)
                    ldm4t(vf[g], &Vc[(ro + j * 16 + lrow) * 72 + g * 16 + lcol]);
#pragma unroll
                for (int g = 0; g < 4; g++) {
                    mma16(Oa[2 * g], pa, vf[g][0], vf[g][1]);
                    mma16(Oa[2 * g + 1], pa, vf[g][2], vf[g][3]);
                }
            }
        }
        rs0 += __shfl_xor_sync(0xffffffffu, rs0, 1);
        rs0 += __shfl_xor_sync(0xffffffffu, rs0, 2);
        rs1 += __shfl_xor_sync(0xffffffffu, rs1, 1);
        rs1 += __shfl_xor_sync(0xffffffffu, rs1, 2);
        lsum0 += rs0;
        lsum1 += rs1;
    }

    float inv0 = 1.f / lsum0, inv1 = 1.f / lsum1;
    int n0 = qt * 128 + w * 16 + r;
    size_t b0 = (((size_t)(b * NN + n0)) * HH + h) * DD;
    size_t b1 = (((size_t)(b * NN + n0 + 8)) * HH + h) * DD;
#pragma unroll
    for (int ni = 0; ni < 8; ni++) {
        *(__half2*)&g_attn[b0 + ni * 8 + 2 * q] =
            __floats2half2_rn(Oa[ni][0] * inv0, Oa[ni][1] * inv0);
        *(__half2*)&g_attn[b1 + ni * 8 + 2 * q] =
            __floats2half2_rn(Oa[ni][2] * inv1, Oa[ni][3] * inv1);
    }
}

extern "C" void kernel_launch(void* const* d_in, const int* in_sizes, int n_in,
                              void* d_out, int out_size) {
    const float* x = (const float*)d_in[0];
    const float* w_qkv = (const float*)d_in[1];
    const float* w_proj = (const float*)d_in[2];
    const float* b_proj = (const float*)d_in[3];
    float* out = (float*)d_out;

    const int smem0 = NSTG * (A_STG_H + 32 * (96 + 8)) * 2;
    const int smem1 = NSTG * (A_STG_H + 32 * (128 + 8)) * 2;
    cudaFuncSetAttribute(gemm_f16<0, 96>,
                         cudaFuncAttributeMaxDynamicSharedMemorySize, smem0);
    cudaFuncSetAttribute(gemm_f16<1, 128>,
                         cudaFuncAttributeMaxDynamicSharedMemorySize, smem1);
    cudaFuncSetAttribute(attn_f16, cudaFuncAttributeMaxDynamicSharedMemorySize,
                         ATTN_SMEM);

    __half* gx;  cudaGetSymbolAddress((void**)&gx, g_x);
    __half* gwq; cudaGetSymbolAddress((void**)&gwq, g_wqkv);
    __half* gwp; cudaGetSymbolAddress((void**)&gwp, g_wproj);

    conv_all<<<12288, 256>>>(x, w_qkv, w_proj, gx, gwq, gwp);

    gemm_f16<0, 96><<<dim3(32, 64), 256, smem0>>>(nullptr, nullptr);
    attn_f16<<<dim3(8, 16, 8), 256, ATTN_SMEM>>>();
    gemm_f16<1, 128><<<dim3(8, 64), 256, smem1>>>(b_proj, out);
}

// round 17
// speedup vs baseline: 1.0291x; 1.0291x over previous
#include <cuda_runtime.h>
#include <cuda_fp16.h>
#include <math.h>
#include <stdint.h>

#define BB 8
#define NN 1024
#define CC 1024
#define HH 16
#define DD 64

// Scratch (allocation-free rule: __device__ globals)
__device__ __half g_q[BB * HH * NN * DD];
__device__ __half g_k[BB * HH * NN * DD];
__device__ __half g_v[BB * HH * NN * DD];
__device__ __half g_attn[BB * NN * CC];
__device__ __half g_x[BB * NN * CC];
__device__ __half g_wqkv[CC * 3 * CC];    // [k][n] f16 (natural layout)
__device__ __half g_wproj[CC * CC];       // [k][n] f16

__device__ __forceinline__ void mma16(float* d, const uint32_t* a, uint32_t b0,
                                      uint32_t b1) {
    asm volatile(
        "mma.sync.aligned.m16n8k16.row.col.f32.f16.f16.f32 "
        "{%0,%1,%2,%3}, {%4,%5,%6,%7}, {%8,%9}, {%0,%1,%2,%3};\n"
        : "+f"(d[0]), "+f"(d[1]), "+f"(d[2]), "+f"(d[3])
        : "r"(a[0]), "r"(a[1]), "r"(a[2]), "r"(a[3]), "r"(b0), "r"(b1));
}

__device__ __forceinline__ void ldm4a(uint32_t* r, uint32_t a) {
    asm volatile(
        "ldmatrix.sync.aligned.m8n8.x4.shared.b16 {%0,%1,%2,%3}, [%4];\n"
        : "=r"(r[0]), "=r"(r[1]), "=r"(r[2]), "=r"(r[3])
        : "r"(a));
}
__device__ __forceinline__ void ldm4(uint32_t* r, const __half* p) {
    ldm4a(r, (uint32_t)__cvta_generic_to_shared(p));
}
__device__ __forceinline__ void ldm4ta(uint32_t* r, uint32_t a) {
    asm volatile(
        "ldmatrix.sync.aligned.m8n8.x4.trans.shared.b16 {%0,%1,%2,%3}, [%4];\n"
        : "=r"(r[0]), "=r"(r[1]), "=r"(r[2]), "=r"(r[3])
        : "r"(a));
}
__device__ __forceinline__ void ldm4t(uint32_t* r, const __half* p) {
    ldm4ta(r, (uint32_t)__cvta_generic_to_shared(p));
}

// exp2 of two pre-scaled floats, packed f16x2 {lo=exp2(a), hi=exp2(b)}
__device__ __forceinline__ uint32_t exp2h2(float a, float b) {
    uint32_t d;
    asm("{\n\t.reg .b32 t;\n\t"
        "cvt.rn.f16x2.f32 t, %2, %1;\n\t"
        "ex2.approx.f16x2 %0, t;\n\t}"
        : "=r"(d)
        : "f"(a), "f"(b));
    return d;
}

__device__ __forceinline__ void cp16(__half* smem, const __half* gmem) {
    uint32_t s = (uint32_t)__cvta_generic_to_shared(smem);
    asm volatile("cp.async.cg.shared.global [%0], [%1], 16;\n" ::"r"(s), "l"(gmem)
                 : "memory");
}
__device__ __forceinline__ void cp_commit() {
    asm volatile("cp.async.commit_group;\n" ::: "memory");
}
template <int N>
__device__ __forceinline__ void cp_wait() {
    asm volatile("cp.async.wait_group %0;\n" ::"n"(N) : "memory");
}

// ---------------------------------------------------------------------------
// Merged pre-pass: f32 -> f16 for x, w_qkv, w_proj in one launch.
// ---------------------------------------------------------------------------
__global__ void conv_all(const float* __restrict__ x, const float* __restrict__ wq,
                         const float* __restrict__ wp, __half* __restrict__ gx,
                         __half* __restrict__ gwq, __half* __restrict__ gwp) {
    int bb = blockIdx.x;
    const float* in;
    __half* out;
    int base;
    if (bb < 8192) {
        in = x; out = gx; base = bb;
    } else if (bb < 11264) {
        in = wq; out = gwq; base = bb - 8192;
    } else {
        in = wp; out = gwp; base = bb - 11264;
    }
    int i = base * 256 + threadIdx.x;
    float4 v = ((const float4*)in)[i];
    ((__half2*)out)[2 * i] = __floats2half2_rn(v.x, v.y);
    ((__half2*)out)[2 * i + 1] = __floats2half2_rn(v.z, v.w);
}

// ---------------------------------------------------------------------------
// fp16 mma.sync GEMM. CTA tile 128 x TN, 8 warps (4m x 2n), k-step 32,
// (TN==128 ? 5 : 6)-stage cp.async ring, ONE stage per barrier (proven best).
// A [m][k] ldmatrix, B [k][n] natural layout via ldmatrix.trans.
// MODE 0: Y = x @ w_qkv, fused RoPE -> g_q/g_k/g_v (f16).   (TN=96)
// MODE 1: out = attn @ w_proj + bias (f32).                  (TN=128)
// ---------------------------------------------------------------------------
#define TSH 40
#define A_STG_H (128 * TSH)
#define A_STG_B (A_STG_H * 2)

template <int MODE, int TN>
__global__ __launch_bounds__(256, 2) void gemm_f16(const float* __restrict__ bias,
                                                   float* __restrict__ out) {
    constexpr int NS = (TN == 128) ? 5 : 6;
    constexpr int BSTR = TN + 8;
    constexpr int B_STG_H = 32 * BSTR;
    constexpr int B_STG_B = B_STG_H * 2;
    constexpr int NB = TN / 32;
    constexpr int NACC = TN / 16;
    constexpr int NCOL = (MODE == 0) ? 3072 : 1024;
    extern __shared__ __half smh[];

    const int tid = threadIdx.x;
    const int bx = blockIdx.x, by = blockIdx.y;
    const int lane = tid & 31, warp = tid >> 5;
    const int wm = warp & 3, wn = warp >> 2;
    const int r = lane >> 2, q = lane & 3;
    const int lrow = lane & 15, lcol = (lane >> 4) * 8;

    const uint32_t sA = (uint32_t)__cvta_generic_to_shared(smh);
    const uint32_t aBase = sA + ((wm * 32 + lrow) * TSH + lcol) * 2;
    const uint32_t bBase =
        sA + NS * A_STG_B + (lrow * BSTR + wn * (TN / 2) + lcol) * 2;

    float acc[2][NACC][4];
#pragma unroll
    for (int mi = 0; mi < 2; mi++)
#pragma unroll
        for (int ni = 0; ni < NACC; ni++)
#pragma unroll
            for (int c = 0; c < 4; c++) acc[mi][ni][c] = 0.f;

    const int srow = tid >> 1, soff = (tid & 1) * 16;
    const __half* Ap = (MODE == 0) ? g_x : g_attn;
    const __half* Bp = (MODE == 0) ? g_wqkv : g_wproj;
    const __half* Ag = Ap + (size_t)(by * 128 + srow) * 1024 + soff;
    __half* AsW = smh + srow * TSH + soff;

    constexpr int BCH = TN / 8;  // 16B chunks per B k-row
    const int b0r = tid / BCH, b0c = (tid % BCH) * 8;
    const int b1r = (tid + 256) / BCH, b1c = ((tid + 256) % BCH) * 8;
    const bool b1act = (TN == 128) || ((TN == 96) && (tid < 128));
    const __half* Bg = Bp + (size_t)bx * TN;
    __half* BsW = smh + NS * A_STG_H;

    auto load_stage = [&](int st, int it) {
        const int k0 = it * 32;
#pragma unroll
        for (int l = 0; l < 2; l++)
            cp16(AsW + st * A_STG_H + l * 8, Ag + k0 + l * 8);
        cp16(BsW + st * B_STG_H + b0r * BSTR + b0c,
             Bg + (size_t)(k0 + b0r) * NCOL + b0c);
        if (b1act)
            cp16(BsW + st * B_STG_H + b1r * BSTR + b1c,
                 Bg + (size_t)(k0 + b1r) * NCOL + b1c);
        cp_commit();
    };

#pragma unroll
    for (int s = 0; s < NS - 1; s++) load_stage(s, s);

    for (int it = 0; it < 32; it++) {
        if (it <= 33 - NS) cp_wait<NS - 2>();
        else if (it == 34 - NS) cp_wait<(NS >= 5) ? NS - 3 : 0>();
        else if (it == 35 - NS) cp_wait<(NS >= 4) ? NS - 4 : 0>();
        else if (NS == 6 && it == 30) cp_wait<1>();
        else cp_wait<0>();
        __syncthreads();
        if (it + NS - 1 < 32) load_stage((it + NS - 1) % NS, it + NS - 1);

        const uint32_t aCur = aBase + (it % NS) * A_STG_B;
        const uint32_t bCur = bBase + (it % NS) * B_STG_B;

        uint32_t fa0[2][4], fa1[2][4], fb0[NB][4], fb1[NB][4];
#pragma unroll
        for (int mi = 0; mi < 2; mi++) ldm4a(fa0[mi], aCur + mi * (16 * TSH * 2));
#pragma unroll
        for (int nb = 0; nb < NB; nb++) ldm4ta(fb0[nb], bCur + nb * 32);
#pragma unroll
        for (int mi = 0; mi < 2; mi++)
            ldm4a(fa1[mi], aCur + mi * (16 * TSH * 2) + 32);
#pragma unroll
        for (int nb = 0; nb < NB; nb++)
            ldm4ta(fb1[nb], bCur + 16 * BSTR * 2 + nb * 32);

#pragma unroll
        for (int mi = 0; mi < 2; mi++)
#pragma unroll
            for (int nb = 0; nb < NB; nb++) {
                mma16(acc[mi][2 * nb], fa0[mi], fb0[nb][0], fb0[nb][1]);
                mma16(acc[mi][2 * nb + 1], fa0[mi], fb0[nb][2], fb0[nb][3]);
            }
#pragma unroll
        for (int mi = 0; mi < 2; mi++)
#pragma unroll
            for (int nb = 0; nb < NB; nb++) {
                mma16(acc[mi][2 * nb], fa1[mi], fb1[nb][0], fb1[nb][1]);
                mma16(acc[mi][2 * nb + 1], fa1[mi], fb1[nb][2], fb1[nb][3]);
            }
    }

#pragma unroll
    for (int mi = 0; mi < 2; mi++)
#pragma unroll
        for (int ni = 0; ni < NACC; ni++)
#pragma unroll
            for (int ch = 0; ch < 2; ch++) {
                int gr = by * 128 + wm * 32 + mi * 16 + ch * 8 + r;
                int gc = bx * TN + wn * (TN / 2) + ni * 8 + 2 * q;
                float v1 = acc[mi][ni][ch * 2], v2 = acc[mi][ni][ch * 2 + 1];
                if (MODE == 1) {
                    float2 o = make_float2(v1 + bias[gc], v2 + bias[gc + 1]);
                    *(float2*)&out[(size_t)gr * 1024 + gc] = o;
                } else {
                    int b = gr >> 10, n = gr & 1023;
                    int which = gc >> 10, within = gc & 1023;
                    int h = within >> 6, d = within & 63;
                    size_t idx = (((size_t)(b * HH + h)) * NN + n) * DD + d;
                    if (which == 2) {
                        __half2 o = __floats2half2_rn(v1, v2);
                        *(__half2*)&g_v[idx] = o;
                    } else {
                        int p = d >> 1;
                        float omega = exp2f(-0.41524101186f * (float)p);
                        float ang = (float)n * omega;
                        float si, co;
                        __sincosf(ang, &si, &co);
                        __half2 o = __floats2half2_rn(v1 * co - v2 * si,
                                                      v2 * co + v1 * si);
                        __half* dst = which ? g_k : g_q;
                        *(__half2*)&dst[idx] = o;
                    }
                }
            }
}

// ---------------------------------------------------------------------------
// fp16 mma.sync flash attention (R13 best). CTA = 128 q-rows of one (b,h).
// Q fragments from global; 3-stage ring of 128-key K/V tiles, prefetch
// distance 2, cp_wait<1>. One barrier + one shfl reduction per 128 keys.
// ---------------------------------------------------------------------------
#define KV2_H (128 * 72)
#define ATTN_SMEM (6 * KV2_H * 2)

__global__ __launch_bounds__(256, 2) void attn_f16() {
    extern __shared__ __half smh[];
    __half* Ks = smh;                 // [3][128][72]
    __half* Vs = smh + 3 * KV2_H;     // [3][128][72]

    const int tid = threadIdx.x;
    const int lane = tid & 31, w = tid >> 5;
    const int r = lane >> 2, q = lane & 3;
    const int lrow = lane & 15, lcol = (lane >> 4) * 8;
    const int qt = blockIdx.x, h = blockIdx.y, b = blockIdx.z;

    const __half* Qg = g_q + ((size_t)(b * HH + h) * NN + qt * 128) * DD;
    const __half* Kg = g_k + (size_t)(b * HH + h) * NN * DD;
    const __half* Vg = g_v + (size_t)(b * HH + h) * NN * DD;

    auto load_kv2 = [&](int kt2, int st) {
#pragma unroll
        for (int l = 0; l < 4; l++) {
            int c = tid + 256 * l;
            int row = c >> 3, ch = c & 7;
            cp16(&Ks[st * KV2_H + row * 72 + ch * 8],
                 Kg + (size_t)(kt2 * 128 + row) * DD + ch * 8);
            cp16(&Vs[st * KV2_H + row * 72 + ch * 8],
                 Vg + (size_t)(kt2 * 128 + row) * DD + ch * 8);
        }
        cp_commit();
    };

    load_kv2(0, 0);
    load_kv2(1, 1);

    uint32_t qf[4][4];
#pragma unroll
    for (int j = 0; j < 4; j++) {
        qf[j][0] = *(const uint32_t*)&Qg[(w * 16 + r) * DD + j * 16 + 2 * q];
        qf[j][1] = *(const uint32_t*)&Qg[(w * 16 + 8 + r) * DD + j * 16 + 2 * q];
        qf[j][2] = *(const uint32_t*)&Qg[(w * 16 + r) * DD + j * 16 + 8 + 2 * q];
        qf[j][3] = *(const uint32_t*)&Qg[(w * 16 + 8 + r) * DD + j * 16 + 8 + 2 * q];
    }

    float Oa[8][4];
#pragma unroll
    for (int ni = 0; ni < 8; ni++)
#pragma unroll
        for (int c = 0; c < 4; c++) Oa[ni][c] = 0.f;
    float lsum0 = 0.f, lsum1 = 0.f;
    const float SC = 0.18033688011f;  // 0.125 * log2(e)

    for (int i = 0; i < 8; i++) {
        if (i < 6) cp_wait<1>(); else cp_wait<0>();
        __syncthreads();
        if (i + 2 < 8) load_kv2(i + 2, (i + 2) % 3);

        const __half* Kc = Ks + (i % 3) * KV2_H;
        const __half* Vc = Vs + (i % 3) * KV2_H;

        float rs0 = 0.f, rs1 = 0.f;
#pragma unroll
        for (int half = 0; half < 2; half++) {
            const int ro = half * 64;
            float s[8][4];
#pragma unroll
            for (int ni = 0; ni < 8; ni++)
#pragma unroll
                for (int c = 0; c < 4; c++) s[ni][c] = 0.f;
#pragma unroll
            for (int j = 0; j < 4; j++) {
                uint32_t kf[4][4];
#pragma unroll
                for (int nb = 0; nb < 4; nb++)
                    ldm4(kf[nb],
                         &Kc[(ro + nb * 16 + lrow) * 72 + j * 16 + lcol]);
#pragma unroll
                for (int nb = 0; nb < 4; nb++) {
                    mma16(s[2 * nb], qf[j], kf[nb][0], kf[nb][2]);
                    mma16(s[2 * nb + 1], qf[j], kf[nb][1], kf[nb][3]);
                }
            }

#pragma unroll
            for (int j = 0; j < 4; j++) {
                uint32_t pa[4];
                pa[0] = exp2h2(s[2 * j][0] * SC, s[2 * j][1] * SC);
                pa[1] = exp2h2(s[2 * j][2] * SC, s[2 * j][3] * SC);
                pa[2] = exp2h2(s[2 * j + 1][0] * SC, s[2 * j + 1][1] * SC);
                pa[3] = exp2h2(s[2 * j + 1][2] * SC, s[2 * j + 1][3] * SC);
                __half2 h0 = __hadd2(*(__half2*)&pa[0], *(__half2*)&pa[2]);
                __half2 h1 = __hadd2(*(__half2*)&pa[1], *(__half2*)&pa[3]);
                rs0 += __low2float(h0) + __high2float(h0);
                rs1 += __low2float(h1) + __high2float(h1);

                uint32_t vf[4][4];
#pragma unroll
                for (int g = 0; g < 4; g++)
                    ldm4t(vf[g], &Vc[(ro + j * 16 + lrow) * 72 + g * 16 + lcol]);
#pragma unroll
                for (int g = 0; g < 4; g++) {
                    mma16(Oa[2 * g], pa, vf[g][0], vf[g][1]);
                    mma16(Oa[2 * g + 1], pa, vf[g][2], vf[g][3]);
                }
            }
        }
        rs0 += __shfl_xor_sync(0xffffffffu, rs0, 1);
        rs0 += __shfl_xor_sync(0xffffffffu, rs0, 2);
        rs1 += __shfl_xor_sync(0xffffffffu, rs1, 1);
        rs1 += __shfl_xor_sync(0xffffffffu, rs1, 2);
        lsum0 += rs0;
        lsum1 += rs1;
    }

    float inv0 = 1.f / lsum0, inv1 = 1.f / lsum1;
    int n0 = qt * 128 + w * 16 + r;
    size_t b0 = (((size_t)(b * NN + n0)) * HH + h) * DD;
    size_t b1 = (((size_t)(b * NN + n0 + 8)) * HH + h) * DD;
#pragma unroll
    for (int ni = 0; ni < 8; ni++) {
        *(__half2*)&g_attn[b0 + ni * 8 + 2 * q] =
            __floats2half2_rn(Oa[ni][0] * inv0, Oa[ni][1] * inv0);
        *(__half2*)&g_attn[b1 + ni * 8 + 2 * q] =
            __floats2half2_rn(Oa[ni][2] * inv1, Oa[ni][3] * inv1);
    }
}

extern "C" void kernel_launch(void* const* d_in, const int* in_sizes, int n_in,
                              void* d_out, int out_size) {
    const float* x = (const float*)d_in[0];
    const float* w_qkv = (const float*)d_in[1];
    const float* w_proj = (const float*)d_in[2];
    const float* b_proj = (const float*)d_in[3];
    float* out = (float*)d_out;

    const int smem0 = 6 * (A_STG_H + 32 * (96 + 8)) * 2;
    const int smem1 = 5 * (A_STG_H + 32 * (128 + 8)) * 2;
    cudaFuncSetAttribute(gemm_f16<0, 96>,
                         cudaFuncAttributeMaxDynamicSharedMemorySize, smem0);
    cudaFuncSetAttribute(gemm_f16<1, 128>,
                         cudaFuncAttributeMaxDynamicSharedMemorySize, smem1);
    cudaFuncSetAttribute(attn_f16, cudaFuncAttributeMaxDynamicSharedMemorySize,
                         ATTN_SMEM);

    __half* gx;  cudaGetSymbolAddress((void**)&gx, g_x);
    __half* gwq; cudaGetSymbolAddress((void**)&gwq, g_wqkv);
    __half* gwp; cudaGetSymbolAddress((void**)&gwp, g_wproj);

    conv_all<<<12288, 256>>>(x, w_qkv, w_proj, gx, gwq, gwp);

    gemm_f16<0, 96><<<dim3(32, 64), 256, smem0>>>(nullptr, nullptr);
    attn_f16<<<dim3(8, 16, 8), 256, ATTN_SMEM>>>();
    gemm_f16<1, 128><<<dim3(8, 64), 256, smem1>>>(b_proj, out);
}